// round 17
// baseline (speedup 1.0000x reference)
#include <cuda_runtime.h>
#include <cuda_bf16.h>
#include <cuda_fp16.h>
#include <cstdint>

#define N_NODES 10000
#define NPAD 10240                // padded node count for stage-1 tiles
#define N_EDGES 64000
#define N_GRAPHS 64
#define HID 64
#define NTILES 500                // 128-edge tiles (edge MLP)
#define NSLICE 65                 // 64 w2 slices + 1 bias slice
#define FRAG_PER_SLICE 512        // 4 kt x 4 np x 32 lanes, uint4 each = 8KB

// ---------------- scratch (device globals; no allocation allowed) ----------------
__device__ float    g_h0[N_NODES * HID];
__device__ float    g_h1[N_NODES * HID];
__device__ float    g_agg[N_NODES * HID];
__device__ __half   g_tt1[N_EDGES * HID];         // edge-MLP layer1 (fp16): [e][k]
__device__ __half   g_tt2[N_EDGES * HID];         // edge-MLP layer2 (fp16): [e][k]
__device__ uint32_t g_hc[NPAD * 32];              // fp16 copy of current h: [n][i/2] (pad rows stay 0)
__device__ uint4    g_bfrag[2 * NSLICE * FRAG_PER_SLICE]; // w2 (+bias) mma-fragment order
__device__ __half   g_G[(size_t)NPAD * NSLICE * 64];      // stage-1 output: [n][s][o]
__device__ int      g_src[N_EDGES];
__device__ int      g_dst[N_EDGES];
__device__ int      g_bat[N_NODES];
__device__ int      g_deg[N_NODES];
__device__ int      g_off[N_NODES + 1];
__device__ int      g_cur[N_NODES];
__device__ int      g_eid[N_EDGES];
__device__ float    g_hg[N_GRAPHS * HID];

// ---------------- aux stream/events (created at static-init; reused every call) ----------------
struct Aux {
    cudaStream_t s1;
    cudaEvent_t fork, join;
    Aux() {
        cudaStreamCreateWithFlags(&s1, cudaStreamNonBlocking);
        cudaEventCreateWithFlags(&fork, cudaEventDisableTiming);
        cudaEventCreateWithFlags(&join, cudaEventDisableTiming);
    }
};
static Aux g_aux;

__device__ __forceinline__ float lrelu(float v) { return v > 0.f ? v : 0.01f * v; }

// ---------------- PTX helpers ----------------
__device__ __forceinline__ void cp16(void* s, const void* g) {
    unsigned sa = (unsigned)__cvta_generic_to_shared(s);
    asm volatile("cp.async.cg.shared.global [%0], [%1], 16;" :: "r"(sa), "l"(g));
}
__device__ __forceinline__ void cp_commit() { asm volatile("cp.async.commit_group;"); }

// fp16 mma: D[16x8] += A[16x16] * B[16x8]
__device__ __forceinline__ void mma16(float* c, const uint32_t* a, uint32_t b0, uint32_t b1) {
    asm volatile(
        "mma.sync.aligned.m16n8k16.row.col.f32.f16.f16.f32 "
        "{%0,%1,%2,%3}, {%4,%5,%6,%7}, {%8,%9}, {%0,%1,%2,%3};"
        : "+f"(c[0]), "+f"(c[1]), "+f"(c[2]), "+f"(c[3])
        : "r"(a[0]), "r"(a[1]), "r"(a[2]), "r"(a[3]), "r"(b0), "r"(b1));
}

// vectorized global reduction (sm_90+)
__device__ __forceinline__ void red2(float* p, float x, float y) {
    asm volatile("red.global.add.v2.f32 [%0], {%1, %2};" :: "l"(p), "f"(x), "f"(y) : "memory");
}

__device__ __forceinline__ uint32_t pack_h2(float a, float b) {
    __half2 hv = __floats2half2_rn(a, b);
    return *reinterpret_cast<uint32_t*>(&hv);
}

// ---------------- zero degree counters ----------------
__global__ void zero_deg_kernel() {
    int id = blockIdx.x * blockDim.x + threadIdx.x;
    if (id < N_NODES) g_deg[id] = 0;
}

// ---------------- index conversion + src histogram + hg zero ----------------
__global__ void convert_idx_kernel(const void* ei, const void* bat) {
    __shared__ int s64;
    if (threadIdx.x == 0) {
        const unsigned* w = (const unsigned*)ei;
        int z = 0;
        for (int i = 1; i < 256; i += 2) z += (w[i] == 0u);
        s64 = (z > 64);
    }
    __syncthreads();
    const bool is64 = (s64 != 0);
    int stride = blockDim.x * gridDim.x;
    int gid = blockIdx.x * blockDim.x + threadIdx.x;
    for (int g = gid; g < N_EDGES; g += stride) {
        int s, d;
        if (is64) {
            s = (int)((const long long*)ei)[g];
            d = (int)((const long long*)ei)[N_EDGES + g];
        } else {
            s = ((const int*)ei)[g];
            d = ((const int*)ei)[N_EDGES + g];
        }
        g_src[g] = s;
        g_dst[g] = d;
        atomicAdd(&g_deg[s], 1);
    }
    for (int g = gid; g < N_NODES; g += stride) {
        g_bat[g] = is64 ? (int)((const long long*)bat)[g] : ((const int*)bat)[g];
    }
    if (gid < N_GRAPHS * HID) g_hg[gid] = 0.f;
}

// ---------------- exclusive prefix sum of degrees (1 CTA) ----------------
__global__ void scan_kernel() {
    __shared__ int ps[1024];
    const int tid = threadIdx.x;
    int loc[10];
    int s = 0;
#pragma unroll
    for (int i = 0; i < 10; ++i) {
        int idx = tid * 10 + i;
        loc[i] = s;
        s += (idx < N_NODES) ? g_deg[idx] : 0;
    }
    ps[tid] = s;
    __syncthreads();
    for (int d = 1; d < 1024; d <<= 1) {
        int v = (tid >= d) ? ps[tid - d] : 0;
        __syncthreads();
        ps[tid] += v;
        __syncthreads();
    }
    int off = (tid == 0) ? 0 : ps[tid - 1];
#pragma unroll
    for (int i = 0; i < 10; ++i) {
        int idx = tid * 10 + i;
        if (idx < N_NODES) {
            g_off[idx] = off + loc[i];
            g_cur[idx] = off + loc[i];
        }
    }
    if (tid == 1023) g_off[N_NODES] = ps[1023];
}

// ---------------- CSR scatter: edges grouped by src ----------------
__global__ void csr_kernel() {
    int e = blockIdx.x * blockDim.x + threadIdx.x;
    if (e >= N_EDGES) return;
    int pos = atomicAdd(&g_cur[g_src[e]], 1);
    g_eid[pos] = e;
}

// ---------------- node encoder: 32 nodes/CTA; emits fp16 copy; zeroes agg ----------------
__global__ void __launch_bounds__(256) node_enc_kernel(
    const float* __restrict__ x, const float* __restrict__ w,
    const float* __restrict__ b, float* __restrict__ h,
    uint32_t* __restrict__ hc, float* __restrict__ agg) {
    __shared__ float xs[32 * 128];
    __shared__ float ws[128 * 64];
    const int tid = threadIdx.x;
    const int n0 = blockIdx.x * 32;

    for (int idx = tid; idx < 4096; idx += 256) {
        int n = n0 + (idx >> 7);
        xs[idx] = (n < N_NODES) ? x[(size_t)n * 128 + (idx & 127)] : 0.f;
    }
    for (int idx = tid; idx < 8192; idx += 256) ws[idx] = w[idx];
    __syncthreads();

    const int og = tid & 15, nl = tid >> 4;
    const int na = n0 + nl, nb = n0 + nl + 16;
    float4 A = *(const float4*)&b[4 * og];
    float4 B = A;
    const float* xa = xs + nl * 128;
    const float* xb = xs + (nl + 16) * 128;
#pragma unroll 16
    for (int i = 0; i < 128; ++i) {
        float va = xa[i], vb = xb[i];
        float4 wv = *(const float4*)&ws[i * 64 + 4 * og];
        A.x += va * wv.x; A.y += va * wv.y; A.z += va * wv.z; A.w += va * wv.w;
        B.x += vb * wv.x; B.y += vb * wv.y; B.z += vb * wv.z; B.w += vb * wv.w;
    }
    if (na < N_NODES) {
        float4 o;
        o.x = lrelu(A.x); o.y = lrelu(A.y); o.z = lrelu(A.z); o.w = lrelu(A.w);
        *(float4*)&h[(size_t)na * 64 + 4 * og] = o;
        hc[(size_t)na * 32 + 2 * og] = pack_h2(o.x, o.y);
        hc[(size_t)na * 32 + 2 * og + 1] = pack_h2(o.z, o.w);
        *(float4*)&agg[(size_t)na * 64 + 4 * og] = make_float4(0.f, 0.f, 0.f, 0.f);
    }
    if (nb < N_NODES) {
        float4 o;
        o.x = lrelu(B.x); o.y = lrelu(B.y); o.z = lrelu(B.z); o.w = lrelu(B.w);
        *(float4*)&h[(size_t)nb * 64 + 4 * og] = o;
        hc[(size_t)nb * 32 + 2 * og] = pack_h2(o.x, o.y);
        hc[(size_t)nb * 32 + 2 * og + 1] = pack_h2(o.z, o.w);
        *(float4*)&agg[(size_t)nb * 64 + 4 * og] = make_float4(0.f, 0.f, 0.f, 0.f);
    }
}

// ---------------- fused edge MLP (both layers): one thread/edge; writes t rows [e][k] ----------------
__global__ void __launch_bounds__(128) edge_mlp2_kernel(
    const float* __restrict__ ea,
    const float* __restrict__ w1a, const float* __restrict__ b1a,
    const float* __restrict__ w1b, const float* __restrict__ b1b,
    __half* __restrict__ tt1, __half* __restrict__ tt2) {
    __shared__ float eas[128 * 33];
    __shared__ float wA[32 * 64];
    __shared__ float wB[32 * 64];
    __shared__ float bA[64], bB[64];
    const int tid = threadIdx.x;
    const int tile = blockIdx.x;
    for (int idx = tid; idx < 128 * 32; idx += 128) {
        int e = idx >> 5, j = idx & 31;
        eas[e * 33 + j] = ea[tile * 4096 + idx];
    }
    for (int idx = tid; idx < 2048; idx += 128) { wA[idx] = w1a[idx]; wB[idx] = w1b[idx]; }
    if (tid < 64) { bA[tid] = b1a[tid]; bB[tid] = b1b[tid]; }
    __syncthreads();

    float ear[32];
#pragma unroll
    for (int j = 0; j < 32; ++j) ear[j] = eas[tid * 33 + j];

    const size_t e = (size_t)tile * 128 + tid;
    uint32_t* r1 = (uint32_t*)(tt1 + e * 64);
    uint32_t* r2 = (uint32_t*)(tt2 + e * 64);
#pragma unroll 2
    for (int og = 0; og < 16; ++og) {
        float4 a1 = *(const float4*)&bA[4 * og];
        float4 a2 = *(const float4*)&bB[4 * og];
#pragma unroll
        for (int j = 0; j < 32; ++j) {
            float v = ear[j];
            float4 wa = *(const float4*)&wA[j * 64 + 4 * og];
            float4 wb = *(const float4*)&wB[j * 64 + 4 * og];
            a1.x += v * wa.x; a1.y += v * wa.y; a1.z += v * wa.z; a1.w += v * wa.w;
            a2.x += v * wb.x; a2.y += v * wb.y; a2.z += v * wb.z; a2.w += v * wb.w;
        }
        r1[2 * og + 0] = pack_h2(fmaxf(a1.x, 0.f), fmaxf(a1.y, 0.f));
        r1[2 * og + 1] = pack_h2(fmaxf(a1.z, 0.f), fmaxf(a1.w, 0.f));
        r2[2 * og + 0] = pack_h2(fmaxf(a2.x, 0.f), fmaxf(a2.y, 0.f));
        r2[2 * og + 1] = pack_h2(fmaxf(a2.z, 0.f), fmaxf(a2.w, 0.f));
    }
}

// ---------------- B prep (both layers): w2 (+b2) -> mma fragment order ----------------
__global__ void bprep2_kernel(const float* __restrict__ w2a, const float* __restrict__ b2a,
                              const float* __restrict__ w2b, const float* __restrict__ b2b,
                              uint4* __restrict__ bf) {
    int id = blockIdx.x * blockDim.x + threadIdx.x;
    if (id >= 2 * NSLICE * FRAG_PER_SLICE) return;
    int layer = id >= NSLICE * FRAG_PER_SLICE;
    int rid = id - layer * NSLICE * FRAG_PER_SLICE;
    int s = rid >> 9;
    int f = rid & 511;
    int kt = f >> 7, np = (f >> 5) & 3, lane = f & 31;
    int tig = lane & 3, g = lane >> 2;
    const float* w2 = layer ? w2b : w2a;
    const float* b2 = layer ? b2b : b2a;
    int o0 = g + 16 * np, o1 = o0 + 8;
    int p0 = kt * 8 + tig, p1 = p0 + 4;
    auto rd = [&](int i, int o) -> float {
        return (s < 64) ? w2[(s << 12) + (i << 6) + o] : b2[(i << 6) + o];
    };
    auto pk = [&](int p, int o) -> uint32_t {
        return pack_h2(rd(2 * p, o), rd(2 * p + 1, o));
    };
    uint4 v;
    v.x = pk(p0, o0); v.y = pk(p1, o0); v.z = pk(p0, o1); v.w = pk(p1, o1);
    bf[id] = v;
}

// ---------------- stage 1: G[n][s][o] = H[n,:] @ B_s  (per-node GEMM) ----------------
// grid (NPAD/128, 4); CTA = 128 nodes x 16-17 slices; 4 warps
__global__ void __launch_bounds__(128) g1_kernel(
    const uint32_t* __restrict__ hc, const uint4* __restrict__ bf, __half* __restrict__ G) {
    __shared__ uint4 Bs[2][FRAG_PER_SLICE];
    const int tid = threadIdx.x;
    const int w = tid >> 5, lane = tid & 31;
    const int g = lane >> 2, tig = lane & 3;
    const int n0 = blockIdx.x * 128;
    const int s0 = blockIdx.y * 16;
    const int ns = (blockIdx.y == 3) ? 17 : 16;

    {
        const uint4* src = bf + (size_t)s0 * FRAG_PER_SLICE;
#pragma unroll
        for (int q = 0; q < 4; ++q) cp16(&Bs[0][tid + q * 128], src + tid + q * 128);
        cp_commit();
    }

    uint32_t hh[2][2][8];
#pragma unroll
    for (int m = 0; m < 2; ++m)
#pragma unroll
        for (int r = 0; r < 2; ++r) {
            const uint32_t* hp = hc + (size_t)(n0 + w * 32 + m * 16 + r * 8 + g) * 32 + tig;
#pragma unroll
            for (int j = 0; j < 8; ++j) hh[m][r][j] = hp[4 * j];
        }

    for (int si = 0; si < ns; ++si) {
        asm volatile("cp.async.wait_group 0;");
        __syncthreads();
        if (si < ns - 1) {
            const uint4* src = bf + (size_t)(s0 + si + 1) * FRAG_PER_SLICE;
            uint4* d = Bs[(si + 1) & 1];
#pragma unroll
            for (int q = 0; q < 4; ++q) cp16(&d[tid + q * 128], src + tid + q * 128);
            cp_commit();
        }

        float C[2][8][4];
#pragma unroll
        for (int m = 0; m < 2; ++m)
#pragma unroll
            for (int nt = 0; nt < 8; ++nt)
#pragma unroll
                for (int q = 0; q < 4; ++q) C[m][nt][q] = 0.f;

        const uint4* B = Bs[si & 1];
#pragma unroll
        for (int kt = 0; kt < 4; ++kt) {
            uint32_t a[2][4];
#pragma unroll
            for (int m = 0; m < 2; ++m) {
                a[m][0] = hh[m][0][2 * kt + 0];
                a[m][1] = hh[m][1][2 * kt + 0];
                a[m][2] = hh[m][0][2 * kt + 1];
                a[m][3] = hh[m][1][2 * kt + 1];
            }
#pragma unroll
            for (int np = 0; np < 4; ++np) {
                uint4 bv = B[(kt * 4 + np) * 32 + lane];
                mma16(C[0][2 * np + 0], a[0], bv.x, bv.y);
                mma16(C[1][2 * np + 0], a[1], bv.x, bv.y);
                mma16(C[0][2 * np + 1], a[0], bv.z, bv.w);
                mma16(C[1][2 * np + 1], a[1], bv.z, bv.w);
            }
        }

        const int s = s0 + si;
#pragma unroll
        for (int m = 0; m < 2; ++m) {
            const int nA = n0 + w * 32 + m * 16 + g;
            __half* pA = G + (size_t)nA * (NSLICE * 64) + s * 64 + 2 * tig;
            __half* pB = pA + (size_t)8 * (NSLICE * 64);
#pragma unroll
            for (int nt = 0; nt < 8; ++nt) {
                *(uint32_t*)(pA + nt * 8) = pack_h2(C[m][nt][0], C[m][nt][1]);
                *(uint32_t*)(pB + nt * 8) = pack_h2(C[m][nt][2], C[m][nt][3]);
            }
        }
    }
}

// ---------------- stage 2: per-node t-weighted combine + scatter ----------------
// warp per node; G row staged in SMEM; lane owns output pair o = 2*lane
__global__ void __launch_bounds__(128) g2_kernel(
    const __half* __restrict__ G, const __half* __restrict__ tt, float* __restrict__ agg) {
    __shared__ __align__(16) __half Gs[4][NSLICE * 64];
    const int tid = threadIdx.x;
    const int w = tid >> 5, lane = tid & 31;
    const int n = blockIdx.x * 4 + w;
    if (n >= N_NODES) return;
    const int beg = g_off[n], end = g_off[n + 1];
    if (beg == end) return;

    const __half* gp = G + (size_t)n * (NSLICE * 64);
    for (int c = lane; c < NSLICE * 8; c += 32) cp16(&Gs[w][c * 8], gp + c * 8);
    cp_commit();
    asm volatile("cp.async.wait_group 0;");
    __syncwarp();

    float2 bias2;
    {
        __half2 hv = *(const __half2*)&Gs[w][64 * 64 + 2 * lane];
        bias2 = __half22float2(hv);
    }

    for (int i = beg; i < end; ++i) {
        const int eid = g_eid[i];
        const uint32_t tr = ((const uint32_t*)(tt + (size_t)eid * 64))[lane];
        float2 acc0 = bias2;
        float2 acc1 = make_float2(0.f, 0.f);
#pragma unroll
        for (int s2 = 0; s2 < 32; ++s2) {
            uint32_t tu = __shfl_sync(0xffffffffu, tr, s2);
            __half2 tp = *(__half2*)&tu;
            float tv0 = __half2float(__low2half(tp));
            float tv1 = __half2float(__high2half(tp));
            float2 g0 = __half22float2(*(const __half2*)&Gs[w][(2 * s2 + 0) * 64 + 2 * lane]);
            float2 g1 = __half22float2(*(const __half2*)&Gs[w][(2 * s2 + 1) * 64 + 2 * lane]);
            acc0.x += tv0 * g0.x; acc0.y += tv0 * g0.y;
            acc1.x += tv1 * g1.x; acc1.y += tv1 * g1.y;
        }
        acc0.x += acc1.x; acc0.y += acc1.y;
        const int d = g_dst[eid];
        red2(agg + (size_t)d * 64 + 2 * lane, acc0.x, acc0.y);
    }
}

// ---------------- node update: 2 threads/node; emits fp16 copy; zeroes agg ----------------
__global__ void __launch_bounds__(128) node_update_kernel(
    const float* __restrict__ hin, float* __restrict__ agg,
    const float* __restrict__ root, const float* __restrict__ bias,
    float* __restrict__ hout, uint32_t* __restrict__ hc) {
    __shared__ float rs[64 * 64];
    const int tid = threadIdx.x;
    for (int idx = tid; idx < 4096; idx += 128) rs[idx] = root[idx];
    __syncthreads();

    const int half = tid & 1;
    const int n = blockIdx.x * 64 + (tid >> 1);
    if (n >= N_NODES) return;
    const int ob = half * 32;

    float* ap = agg + (size_t)n * 64 + ob;
    float4 acc[8];
#pragma unroll
    for (int q = 0; q < 8; ++q) {
        float4 a = *(const float4*)&ap[4 * q];
        const float4 bv = *(const float4*)&bias[ob + 4 * q];
        a.x += bv.x; a.y += bv.y; a.z += bv.z; a.w += bv.w;
        acc[q] = a;
    }
#pragma unroll
    for (int q = 0; q < 8; ++q)
        *(float4*)&ap[4 * q] = make_float4(0.f, 0.f, 0.f, 0.f);

    const float* hp = hin + (size_t)n * 64;
#pragma unroll
    for (int ig = 0; ig < 4; ++ig) {
        float4 hv[4];
#pragma unroll
        for (int p = 0; p < 4; ++p) hv[p] = *(const float4*)&hp[ig * 16 + 4 * p];
        const float* hr = (const float*)hv;
#pragma unroll
        for (int j = 0; j < 16; ++j) {
            float v = hr[j];
            const float* rr = rs + (ig * 16 + j) * 64 + ob;
#pragma unroll
            for (int q = 0; q < 8; ++q) {
                float4 rv = *(const float4*)&rr[4 * q];
                acc[q].x += v * rv.x; acc[q].y += v * rv.y;
                acc[q].z += v * rv.z; acc[q].w += v * rv.w;
            }
        }
    }

    float* op = hout + (size_t)n * 64 + ob;
    uint32_t* hcp = hc + (size_t)n * 32 + half * 16;
#pragma unroll
    for (int q = 0; q < 8; ++q) {
        float4 o;
        o.x = lrelu(acc[q].x); o.y = lrelu(acc[q].y);
        o.z = lrelu(acc[q].z); o.w = lrelu(acc[q].w);
        *(float4*)&op[4 * q] = o;
        hcp[2 * q] = pack_h2(o.x, o.y);
        hcp[2 * q + 1] = pack_h2(o.z, o.w);
    }
}

// ---------------- global add pool (batch-sorted running-sum flush) ----------------
__global__ void pool_kernel(const float* __restrict__ h) {
    const int tid = threadIdx.x;
    const int o = tid & 63, q = tid >> 6;
    const int nbase = blockIdx.x * 256 + q * 64;
    float run = 0.f;
    int curb = -1;
    for (int j = 0; j < 64; ++j) {
        int n = nbase + j;
        if (n >= N_NODES) break;
        int bn = g_bat[n];
        if (bn != curb) {
            if (curb >= 0) atomicAdd(&g_hg[curb * 64 + o], run);
            run = 0.f;
            curb = bn;
        }
        run += h[(size_t)n * 64 + o];
    }
    if (curb >= 0) atomicAdd(&g_hg[curb * 64 + o], run);
}

// ---------------- readout head ----------------
__global__ void head_kernel(const float* __restrict__ fc1w, const float* __restrict__ fc1b,
                            const float* __restrict__ fc2w, const float* __restrict__ fc2b,
                            float* __restrict__ out) {
    __shared__ float hs[N_GRAPHS * HID];
    int g = threadIdx.x;
    for (int i = g; i < N_GRAPHS * HID; i += 64) hs[i] = g_hg[i];
    __syncthreads();
    float acc = fc2b[0];
#pragma unroll 4
    for (int j = 0; j < 32; ++j) {
        float s = fc1b[j];
#pragma unroll 8
        for (int i = 0; i < 64; ++i) s += hs[g * 64 + i] * fc1w[i * 32 + j];
        acc += lrelu(s) * fc2w[j];
    }
    out[g] = acc;
}

// ---------------- launch ----------------
extern "C" void kernel_launch(void* const* d_in, const int* in_sizes, int n_in,
                              void* d_out, int out_size) {
    const float* x     = (const float*)d_in[0];
    const void*  ei    = d_in[1];
    const float* ea    = (const float*)d_in[2];
    const void*  bat   = d_in[3];
    const float* nfc_w = (const float*)d_in[4];
    const float* nfc_b = (const float*)d_in[5];
    const float* e1w1  = (const float*)d_in[6];
    const float* e1b1  = (const float*)d_in[7];
    const float* e1w2  = (const float*)d_in[8];
    const float* e1b2  = (const float*)d_in[9];
    const float* root1 = (const float*)d_in[10];
    const float* bias1 = (const float*)d_in[11];
    const float* e2w1  = (const float*)d_in[12];
    const float* e2b1  = (const float*)d_in[13];
    const float* e2w2  = (const float*)d_in[14];
    const float* e2b2  = (const float*)d_in[15];
    const float* root2 = (const float*)d_in[16];
    const float* bias2 = (const float*)d_in[17];
    const float* fc1w  = (const float*)d_in[18];
    const float* fc1b  = (const float*)d_in[19];
    const float* fc2w  = (const float*)d_in[20];
    const float* fc2b  = (const float*)d_in[21];
    float* out = (float*)d_out;

    float *h0, *h1, *agg, *hg;
    __half *tt1, *tt2, *G;
    uint32_t* hc;
    uint4* bfp;
    cudaGetSymbolAddress((void**)&h0, g_h0);
    cudaGetSymbolAddress((void**)&h1, g_h1);
    cudaGetSymbolAddress((void**)&agg, g_agg);
    cudaGetSymbolAddress((void**)&tt1, g_tt1);
    cudaGetSymbolAddress((void**)&tt2, g_tt2);
    cudaGetSymbolAddress((void**)&hg, g_hg);
    cudaGetSymbolAddress((void**)&hc, g_hc);
    cudaGetSymbolAddress((void**)&bfp, g_bfrag);
    cudaGetSymbolAddress((void**)&G, g_G);

    // aux: edge MLP + index convert + CSR build (all hidden under main's front)
    cudaEventRecord(g_aux.fork, 0);
    cudaStreamWaitEvent(g_aux.s1, g_aux.fork, 0);
    zero_deg_kernel<<<(N_NODES + 255) / 256, 256, 0, g_aux.s1>>>();
    convert_idx_kernel<<<256, 256, 0, g_aux.s1>>>(ei, bat);
    scan_kernel<<<1, 1024, 0, g_aux.s1>>>();
    csr_kernel<<<(N_EDGES + 255) / 256, 256, 0, g_aux.s1>>>();
    edge_mlp2_kernel<<<NTILES, 128, 0, g_aux.s1>>>(ea, e1w1, e1b1, e2w1, e2b1, tt1, tt2);
    cudaEventRecord(g_aux.join, g_aux.s1);

    // main: encoder + weight prep + stage-1 of layer 1 (none of these need edges)
    node_enc_kernel<<<(N_NODES + 31) / 32, 256>>>(x, nfc_w, nfc_b, h0, hc, agg);
    bprep2_kernel<<<(2 * NSLICE * FRAG_PER_SLICE + 255) / 256, 256>>>(
        e1w2, e1b2, e2w2, e2b2, bfp);
    g1_kernel<<<dim3(NPAD / 128, 4), 128>>>(hc, bfp, G);

    cudaStreamWaitEvent(0, g_aux.join, 0);

    // layer 1: combine + update
    g2_kernel<<<(N_NODES + 3) / 4, 128>>>(G, tt1, agg);
    node_update_kernel<<<(N_NODES + 63) / 64, 128>>>(h0, agg, root1, bias1, h1, hc);

    // layer 2
    g1_kernel<<<dim3(NPAD / 128, 4), 128>>>(hc, bfp + (size_t)NSLICE * FRAG_PER_SLICE, G);
    g2_kernel<<<(N_NODES + 3) / 4, 128>>>(G, tt2, agg);
    node_update_kernel<<<(N_NODES + 63) / 64, 128>>>(h1, agg, root2, bias2, h0, hc);

    // pool + head
    pool_kernel<<<(N_NODES + 255) / 256, 256>>>(h0);
    head_kernel<<<1, 64>>>(fc1w, fc1b, fc2w, fc2b, out);
}